// round 11
// baseline (speedup 1.0000x reference)
#include <cuda_runtime.h>
#include <math.h>

#define BATCH 4
#define DIMC  64
#define HFC   128
#define C2C   256
#define HH    256
#define WWC   256
#define HW    (HH*WWC)   // 65536

typedef unsigned int u32;
typedef unsigned long long u64;

// K12 hs geometry (floats): ch-stride 1160, patch-stride 72
#define HS_CS 1160
#define HS_PS 72
#define XS_S 136
// K34 smem geometry
#define SU_CS 371       // channel stride (floats); 371%32=19 -> conflict-free
#define SU_RS 37        // row stride
#define GS_S  260       // gsm row stride (k row of 256 px + pad)

// ---------------- scratch (device globals: allocation-free rule) -------------
__device__ float  g_u[(size_t)BATCH*C2C*HW];          // spectral output (268 MB)
__device__ float4 g_ga[(size_t)C2C*8*4*32];           // conv-G A-fragments (4 MB)
__device__ float4 g_wa[16*8*32];                      // w_in A-fragments
__device__ u64    g_wo[128*32];                       // packed w_out

// ---------------- helpers ----------------------------------------------------
__device__ __forceinline__ u32 tf32b(float x){
    u32 r; asm("cvt.rna.tf32.f32 %0, %1;" : "=r"(r) : "f"(x)); return r;
}
__device__ __forceinline__ float tf32f(float x){ return __uint_as_float(tf32b(x)); }
__device__ __forceinline__ u32 bits(float x){ return __float_as_uint(x); }

__device__ __forceinline__ void mma8(float* d, u32 a0,u32 a1,u32 a2,u32 a3, u32 b0,u32 b1){
    asm("mma.sync.aligned.m16n8k8.row.col.f32.tf32.tf32.f32 "
        "{%0,%1,%2,%3},{%4,%5,%6,%7},{%8,%9},{%0,%1,%2,%3};"
        : "+f"(d[0]),"+f"(d[1]),"+f"(d[2]),"+f"(d[3])
        : "r"(a0),"r"(a1),"r"(a2),"r"(a3),"r"(b0),"r"(b1));
}

__device__ __forceinline__ u64 pk(float lo, float hi){
    u64 r; asm("mov.b64 %0, {%1,%2};" : "=l"(r) : "f"(lo), "f"(hi)); return r;
}
__device__ __forceinline__ float2 upk(u64 v){
    float2 r; asm("mov.b64 {%0,%1}, %2;" : "=f"(r.x), "=f"(r.y) : "l"(v)); return r;
}
__device__ __forceinline__ void fma2(u64& d, u64 a, u64 b){
    asm("fma.rn.f32x2 %0, %1, %2, %0;" : "+l"(d) : "l"(a), "l"(b));
}

// ---------------- K0: spectral filter -> conv-G MMA A-fragments --------------
// g_c[n1,n2] = (1/64) * sum_{k1,k2} G(k1,k2) cos(pi/4*(k1*n1+k2*n2)),
// G = Hermitian extension of F with symmetrization at k2 in {0,4}.
// Conv matrix Gm[n][m] = g[(n1-m1)&7][(n2-m2)&7];  u_patch = Gm @ h_patch.
__global__ void k0_spectral(const float* __restrict__ filt){
    __shared__ float gs[64];
    int c = blockIdx.x, t = threadIdx.x;
    if (t < 64){
        int n1 = t >> 3, n2 = t & 7;
        const float* F = filt + c*40;   // [8][5]
        float s = 0.f;
        for (int k1=0;k1<8;k1++){
            for (int k2=0;k2<8;k2++){
                float Gv;
                if (k2>=1 && k2<=3)      Gv = F[k1*5+k2];
                else if (k2>=5)          Gv = F[((8-k1)&7)*5 + (8-k2)];
                else                     Gv = 0.5f*(F[k1*5+k2] + F[((8-k1)&7)*5 + k2]);
                int m = (k1*n1 + k2*n2) & 7;
                s += Gv * cospif(0.25f * (float)m);
            }
        }
        gs[t] = s * (1.f/64.f);
    }
    __syncthreads();
    for (int i=t; i<8*4*32; i+=256){
        int kk = i>>7, mt = (i>>5)&3, lane = i&31;
        int lq = lane>>2, la = lane&3;
        int n0 = mt*16+lq, n1r = n0+8;
        int m0 = kk*8+la,  m1c = m0+4;
        #define GM(n,m) gs[ ((((n)>>3)-((m)>>3))&7)*8 + ((((n)&7)-((m)&7))&7) ]
        g_ga[((size_t)(c*8+kk)*4 + mt)*32 + lane] =
            make_float4(tf32f(GM(n0,m0)), tf32f(GM(n1r,m0)),
                        tf32f(GM(n0,m1c)), tf32f(GM(n1r,m1c)));
        #undef GM
    }
}

// ---------------- K0b: pack w_in A-fragments + w_out pairs -------------------
__global__ void k0_packw(const float* __restrict__ w_in, const float* __restrict__ w_out){
    int idx = blockIdx.x*256 + threadIdx.x;      // 16*256 = 4096
    {
        int ocg = idx>>8, kk = (idx>>5)&7, lane = idx&31;
        int lq = lane>>2, la = lane&3;
        int o = ocg*16, k = kk*8;
        g_wa[idx] = make_float4(
            tf32f(w_in[(o+lq)*DIMC + k+la]),
            tf32f(w_in[(o+lq+8)*DIMC + k+la]),
            tf32f(w_in[(o+lq)*DIMC + k+la+4]),
            tf32f(w_in[(o+lq+8)*DIMC + k+la+4]));
    }
    if (idx < 128*32){
        int ii = idx >> 5, j = idx & 31;
        g_wo[idx] = pk(w_out[(2*j)*HFC + ii], w_out[(2*j+1)*HFC + ii]);
    }
}

// ---------------- K12: fused in-proj GEMM + spectral conv GEMM (tf32 MMA) ----
__global__ __launch_bounds__(256, 2) void k12_fused(const float* __restrict__ x){
    extern __shared__ float sm[];
    float* xs = sm;                  // [64][XS_S]
    float* hs = sm + 64*XS_S;        // 16ch x 16p x 64m
    int ocg = blockIdx.x;
    int s   = blockIdx.y;
    int b   = blockIdx.z;
    int t = threadIdx.x, lane = t & 31, w = t >> 5;
    int la = lane & 3, lq = lane >> 2;

    float4 wa[8];
    #pragma unroll
    for (int kk=0;kk<8;kk++) wa[kk] = g_wa[(ocg*8+kk)*32 + lane];

    int s8 = (s>>1)*8, cb = (s&1)*128;
    const float* xb = x + (size_t)b*DIMC*HW + (size_t)s8*WWC + cb;

    int sc = t>>2, seg = t&3;
    for (int r=0; r<8; r++){
        __syncthreads();
        {
            const float4* src = (const float4*)(xb + (size_t)sc*HW + r*WWC) + seg*8;
            float* dst = xs + sc*XS_S + seg*32;
            #pragma unroll
            for (int j=0;j<8;j++){
                float4 v = src[j];
                dst[j*4+0]=tf32f(v.x); dst[j*4+1]=tf32f(v.y);
                dst[j*4+2]=tf32f(v.z); dst[j*4+3]=tf32f(v.w);
            }
        }
        __syncthreads();
        #pragma unroll
        for (int nt=0;nt<2;nt++){
            int p = w*2 + nt;
            float d[4] = {0.f,0.f,0.f,0.f};
            #pragma unroll
            for (int kk=0;kk<8;kk++){
                u32 b0 = bits(xs[(kk*8+la)*XS_S + p*8 + lq]);
                u32 b1 = bits(xs[(kk*8+la+4)*XS_S + p*8 + lq]);
                mma8(d, bits(wa[kk].x),bits(wa[kk].y),bits(wa[kk].z),bits(wa[kk].w), b0,b1);
            }
            int m = r*8 + 2*la;
            *(float2*)&hs[lq*HS_CS     + p*HS_PS + m] = make_float2(tf32f(d[0]), tf32f(d[1]));
            *(float2*)&hs[(lq+8)*HS_CS + p*HS_PS + m] = make_float2(tf32f(d[2]), tf32f(d[3]));
        }
    }
    __syncthreads();

    for (int ci=0; ci<2; ci++){
        int chl = w*2 + ci;
        const float4* ga = &g_ga[((size_t)((ocg*16+chl)*8))*4*32 + lane];
        float d[4][2][4];
        #pragma unroll
        for (int mt=0;mt<4;mt++)
            #pragma unroll
            for (int nt=0;nt<2;nt++){ d[mt][nt][0]=d[mt][nt][1]=d[mt][nt][2]=d[mt][nt][3]=0.f; }
        #pragma unroll
        for (int kk=0;kk<8;kk++){
            u32 b0[2], b1[2];
            #pragma unroll
            for (int nt=0;nt<2;nt++){
                b0[nt] = bits(hs[chl*HS_CS + (nt*8+lq)*HS_PS + kk*8+la]);
                b1[nt] = bits(hs[chl*HS_CS + (nt*8+lq)*HS_PS + kk*8+la+4]);
            }
            #pragma unroll
            for (int mt=0;mt<4;mt++){
                float4 a = ga[(kk*4+mt)*32];
                u32 a0=bits(a.x), a1=bits(a.y), a2=bits(a.z), a3=bits(a.w);
                mma8(d[mt][0], a0,a1,a2,a3, b0[0],b1[0]);
                mma8(d[mt][1], a0,a1,a2,a3, b0[1],b1[1]);
            }
        }
        float* ub = g_u + (size_t)(b*C2C + ocg*16 + chl)*HW + (size_t)s8*WWC + cb;
        #pragma unroll
        for (int mt=0;mt<4;mt++){
            #pragma unroll
            for (int nt=0;nt<2;nt++){
                int c0 = (nt*8 + 2*la)*8 + lq;
                ub[(2*mt)*WWC   + c0]     = d[mt][nt][0];
                ub[(2*mt)*WWC   + c0 + 8] = d[mt][nt][1];
                ub[(2*mt+1)*WWC + c0]     = d[mt][nt][2];
                ub[(2*mt+1)*WWC + c0 + 8] = d[mt][nt][3];
            }
        }
    }
}

// ---------------- K34: fused depthwise 3x3 + GELU gate + out-projection ------
// Block: 8-row x 32-col px tile. Phase A: 8 chunks of 16 channel-pairs ->
// dw conv + gelu gate into gsm[128][GS_S] (f32). Phase B: out[64][256] GEMM
// over k=128 via FMA2. All f32 after g_u (precision-neutral vs split kernels).
__global__ __launch_bounds__(256) void k34_fused(float* __restrict__ out,
                                                 const float* __restrict__ w_dw){
    extern __shared__ float sm[];
    float* su  = sm;                         // [32][SU_CS]   47.5 KB
    float* gsm = sm + 32*SU_CS;              // [128][GS_S]  133.1 KB
    u64*   wsm = (u64*)(sm + 32*SU_CS + 128*GS_S);  // [128][32]  32 KB
    int tx = blockIdx.x, ty = blockIdx.y, b = blockIdx.z;
    int x0 = tx*32, y0 = ty*8;
    int t = threadIdx.x;

    for (int idx=t; idx<128*32; idx+=256) wsm[idx] = g_wo[idx];

    int pr = t & 15, pxg = t >> 4;           // conv map: pair, (row,col-half)
    int rr = pxg >> 1, c0 = (pxg & 1)*16;

    // ---------------- Phase A: per-chunk dw conv + gelu gate ----------------
    for (int c=0; c<8; c++){
        __syncthreads();
        // stage u tiles for 16 pairs (32 channels), rows y0-1..y0+8, cols x0-1..x0+32
        for (int i=0;i<40;i++){
            int idx = i*256 + t;             // 10 rows x 32 ch x 32 cols
            int row = idx>>10, ch = (idx>>5)&31, col = idx&31;
            int gci = (ch<16) ? (c*16+ch) : (c*16+ch-16+HFC);
            int y = y0 + row - 1;
            float v = 0.f;
            if (y>=0 && y<HH) v = g_u[(size_t)(b*C2C+gci)*HW + y*WWC + x0 + col];
            su[ch*SU_CS + row*SU_RS + col + 1] = v;
        }
        for (int idx=t; idx<640; idx+=256){  // halo cols (x0-1, x0+32)
            int row = idx>>6, ch = (idx>>1)&31, side = idx&1;
            int gci = (ch<16) ? (c*16+ch) : (c*16+ch-16+HFC);
            int y = y0 + row - 1;
            int xx = x0 - 1 + side*33;
            float v = 0.f;
            if (y>=0 && y<HH && xx>=0 && xx<WWC) v = g_u[(size_t)(b*C2C+gci)*HW + y*WWC + xx];
            su[ch*SU_CS + row*SU_RS + side*33] = v;
        }
        __syncthreads();

        float wA[9], wB[9];
        #pragma unroll
        for (int k=0;k<9;k++){
            wA[k] = w_dw[(c*16+pr)*9 + k];
            wB[k] = w_dw[(c*16+pr+HFC)*9 + k];
        }
        float dd[2][16];
        #pragma unroll
        for (int h=0;h<2;h++){
            const float* sb = su + (pr + h*16)*SU_CS + rr*SU_RS + c0;
            const float* wv = h ? wB : wA;
            #pragma unroll
            for (int j=0;j<16;j++) dd[h][j]=0.f;
            #pragma unroll
            for (int dy=0;dy<3;dy++){
                float v[18];
                #pragma unroll
                for (int q=0;q<18;q++) v[q] = sb[dy*SU_RS + q];
                #pragma unroll
                for (int j=0;j<16;j++)
                    dd[h][j] = fmaf(wv[dy*3+0], v[j],
                               fmaf(wv[dy*3+1], v[j+1],
                               fmaf(wv[dy*3+2], v[j+2], dd[h][j])));
            }
        }
        float* gr = gsm + (c*16+pr)*GS_S + rr*32 + c0;
        #pragma unroll
        for (int j=0;j<16;j++){
            float a = dd[0][j];
            float ge = 0.5f*a*(1.f + erff(a*0.70710678118654752f));
            gr[j] = ge * dd[1][j];
        }
    }
    __syncthreads();

    // ---------------- Phase B: out-proj GEMM (k=128, FMA2) ------------------
    int pxt = t & 63, ocg = t >> 6;          // 64 px-threads x 4 oc-groups (8 pairs)
    u64 acc[4][8];
    #pragma unroll
    for (int p=0;p<4;p++)
        #pragma unroll
        for (int j=0;j<8;j++) acc[p][j]=0ULL;
    #pragma unroll 4
    for (int k=0;k<128;k++){
        float4 xv = *(const float4*)&gsm[k*GS_S + pxt*4];
        u64 xp0 = pk(xv.x,xv.x), xp1 = pk(xv.y,xv.y);
        u64 xp2 = pk(xv.z,xv.z), xp3 = pk(xv.w,xv.w);
        const u64* wr = &wsm[k*32 + ocg*8];
        #pragma unroll
        for (int j=0;j<8;j++){
            u64 w = wr[j];
            fma2(acc[0][j], xp0, w);
            fma2(acc[1][j], xp1, w);
            fma2(acc[2][j], xp2, w);
            fma2(acc[3][j], xp3, w);
        }
    }
    int r = (pxt*4)>>5, cc = (pxt*4)&31;
    float* ob = out + (size_t)b*DIMC*HW + (y0+r)*WWC + x0 + cc;
    #pragma unroll
    for (int j=0;j<8;j++){
        int jj = ocg*8 + j;
        float2 v0=upk(acc[0][j]), v1=upk(acc[1][j]), v2=upk(acc[2][j]), v3=upk(acc[3][j]);
        *(float4*)&ob[(size_t)(2*jj)*HW]   = make_float4(v0.x, v1.x, v2.x, v3.x);
        *(float4*)&ob[(size_t)(2*jj+1)*HW] = make_float4(v0.y, v1.y, v2.y, v3.y);
    }
}

// -----------------------------------------------------------------------------
extern "C" void kernel_launch(void* const* d_in, const int* in_sizes, int n_in,
                              void* d_out, int out_size){
    const float* x     = (const float*)d_in[0];
    const float* w_in  = (const float*)d_in[1];
    const float* w_dw  = (const float*)d_in[2];
    const float* filt  = (const float*)d_in[3];
    const float* w_out = (const float*)d_in[4];
    float* out = (float*)d_out;

    const int smem12 = (64*XS_S + 16*HS_CS) * 4;
    const int smem34 = (32*SU_CS + 128*GS_S) * 4 + 128*32*8;   // 213376 B
    cudaFuncSetAttribute(k12_fused, cudaFuncAttributeMaxDynamicSharedMemorySize, smem12);
    cudaFuncSetAttribute(k34_fused, cudaFuncAttributeMaxDynamicSharedMemorySize, smem34);

    k0_spectral<<<256, 256>>>(filt);
    k0_packw   <<<16, 256>>>(w_in, w_out);
    k12_fused  <<<dim3(16,64,4), 256, smem12>>>(x);
    k34_fused  <<<dim3(8,32,4),  256, smem34>>>(out, w_dw);
}

// round 12
// speedup vs baseline: 2.2897x; 2.2897x over previous
#include <cuda_runtime.h>
#include <math.h>

#define BATCH 4
#define DIMC  64
#define HFC   128
#define C2C   256
#define HH    256
#define WWC   256
#define HW    (HH*WWC)   // 65536

typedef unsigned int u32;
typedef unsigned long long u64;

// K12 smem geometry (floats)
#define XS2_S 72            // xs row stride: 72%32=8 -> conflict-free B loads
#define H2_PS 72            // hs patch stride
#define H2_CS (8*H2_PS+8)   // 584: hs channel stride

// ---------------- scratch (device globals: allocation-free rule) -------------
__device__ float  g_u[(size_t)BATCH*C2C*HW];          // spectral output (268 MB)
__device__ float  g_g[(size_t)BATCH*HFC*HW];          // gated output    (134 MB)
__device__ float4 g_ga[(size_t)C2C*8*4*32];           // conv-G A-fragments (4 MB)
__device__ float4 g_wa[16*8*32];                      // w_in A-fragments
__device__ u64    g_wo[128*32];                       // packed w_out

// ---------------- helpers ----------------------------------------------------
__device__ __forceinline__ u32 tf32b(float x){
    u32 r; asm("cvt.rna.tf32.f32 %0, %1;" : "=r"(r) : "f"(x)); return r;
}
__device__ __forceinline__ float tf32f(float x){ return __uint_as_float(tf32b(x)); }
__device__ __forceinline__ u32 bits(float x){ return __float_as_uint(x); }

__device__ __forceinline__ void mma8(float* d, u32 a0,u32 a1,u32 a2,u32 a3, u32 b0,u32 b1){
    asm("mma.sync.aligned.m16n8k8.row.col.f32.tf32.tf32.f32 "
        "{%0,%1,%2,%3},{%4,%5,%6,%7},{%8,%9},{%0,%1,%2,%3};"
        : "+f"(d[0]),"+f"(d[1]),"+f"(d[2]),"+f"(d[3])
        : "r"(a0),"r"(a1),"r"(a2),"r"(a3),"r"(b0),"r"(b1));
}

__device__ __forceinline__ u64 pk(float lo, float hi){
    u64 r; asm("mov.b64 %0, {%1,%2};" : "=l"(r) : "f"(lo), "f"(hi)); return r;
}
__device__ __forceinline__ float2 upk(u64 v){
    float2 r; asm("mov.b64 {%0,%1}, %2;" : "=f"(r.x), "=f"(r.y) : "l"(v)); return r;
}
__device__ __forceinline__ void fma2(u64& d, u64 a, u64 b){
    asm("fma.rn.f32x2 %0, %1, %2, %0;" : "+l"(d) : "l"(a), "l"(b));
}

// ---------------- K0: spectral filter -> conv-G MMA A-fragments --------------
// g_c[n1,n2] = (1/64) * sum_{k1,k2} G(k1,k2) cos(pi/4*(k1*n1+k2*n2)),
// G = Hermitian extension of F with symmetrization at k2 in {0,4}.
// Conv matrix Gm[n][m] = g[(n1-m1)&7][(n2-m2)&7];  u_patch = Gm @ h_patch.
__global__ void k0_spectral(const float* __restrict__ filt){
    __shared__ float gs[64];
    int c = blockIdx.x, t = threadIdx.x;
    if (t < 64){
        int n1 = t >> 3, n2 = t & 7;
        const float* F = filt + c*40;   // [8][5]
        float s = 0.f;
        for (int k1=0;k1<8;k1++){
            for (int k2=0;k2<8;k2++){
                float Gv;
                if (k2>=1 && k2<=3)      Gv = F[k1*5+k2];
                else if (k2>=5)          Gv = F[((8-k1)&7)*5 + (8-k2)];
                else                     Gv = 0.5f*(F[k1*5+k2] + F[((8-k1)&7)*5 + k2]);
                int m = (k1*n1 + k2*n2) & 7;
                s += Gv * cospif(0.25f * (float)m);
            }
        }
        gs[t] = s * (1.f/64.f);
    }
    __syncthreads();
    for (int i=t; i<8*4*32; i+=256){
        int kk = i>>7, mt = (i>>5)&3, lane = i&31;
        int lq = lane>>2, la = lane&3;
        int n0 = mt*16+lq, n1r = n0+8;
        int m0 = kk*8+la,  m1c = m0+4;
        #define GM(n,m) gs[ ((((n)>>3)-((m)>>3))&7)*8 + ((((n)&7)-((m)&7))&7) ]
        g_ga[((size_t)(c*8+kk)*4 + mt)*32 + lane] =
            make_float4(tf32f(GM(n0,m0)), tf32f(GM(n1r,m0)),
                        tf32f(GM(n0,m1c)), tf32f(GM(n1r,m1c)));
        #undef GM
    }
}

// ---------------- K0b: pack w_in A-fragments + w_out pairs -------------------
__global__ void k0_packw(const float* __restrict__ w_in, const float* __restrict__ w_out){
    int idx = blockIdx.x*256 + threadIdx.x;      // 16*256 = 4096
    {
        int ocg = idx>>8, kk = (idx>>5)&7, lane = idx&31;
        int lq = lane>>2, la = lane&3;
        int o = ocg*16, k = kk*8;
        g_wa[idx] = make_float4(
            tf32f(w_in[(o+lq)*DIMC + k+la]),
            tf32f(w_in[(o+lq+8)*DIMC + k+la]),
            tf32f(w_in[(o+lq)*DIMC + k+la+4]),
            tf32f(w_in[(o+lq+8)*DIMC + k+la+4]));
    }
    if (idx < 128*32){
        int ii = idx >> 5, j = idx & 31;
        g_wo[idx] = pk(w_out[(2*j)*HFC + ii], w_out[(2*j+1)*HFC + ii]);
    }
}

// ---------------- K12: fused in-proj GEMM + spectral conv GEMM (tf32 MMA) ----
// Block: 16 channels x (8-row x 128-col strip), processed as two 64-col
// half-phases of 8 patches each. 59KB smem -> 3 CTAs/SM (24 warps).
__global__ __launch_bounds__(256, 3) void k12_fused(const float* __restrict__ x){
    extern __shared__ float sm[];
    float* was = sm;                 // [8][32] float4 -> 1024 floats (4KB)
    float* xs  = sm + 1024;          // [64][XS2_S] 18.4KB (one row, 64 px)
    float* hs  = xs + 64*XS2_S;      // 16ch x 8patch x 64m (37.4KB)
    int ocg = blockIdx.x;
    int s   = blockIdx.y;
    int b   = blockIdx.z;
    int t = threadIdx.x, lane = t & 31, w = t >> 5;
    int la = lane & 3, lq = lane >> 2;

    float4* wasv = (float4*)was;
    for (int i=t; i<8*32; i+=256) wasv[i] = g_wa[ocg*8*32 + i];

    int s8 = (s>>1)*8, cbase = (s&1)*128;
    const float* xb = x + (size_t)b*DIMC*HW + (size_t)s8*WWC + cbase;
    float* ub = g_u + (size_t)(b*C2C + ocg*16)*HW + (size_t)s8*WWC + cbase;

    int sc = t>>2, seg = t&3;        // staging: 64 ch x 4 segs of 16 floats
    for (int half=0; half<2; half++){
        int co = half*64;
        // ---- Phase 1: h = W @ x for 8 patches (rows 0..7, cols co..co+63) ----
        for (int r=0; r<8; r++){
            __syncthreads();
            {
                const float4* src = (const float4*)(xb + (size_t)sc*HW + r*WWC + co) + seg*4;
                float* dst = xs + sc*XS2_S + seg*16;
                #pragma unroll
                for (int j=0;j<4;j++){
                    float4 v = src[j];
                    dst[j*4+0]=tf32f(v.x); dst[j*4+1]=tf32f(v.y);
                    dst[j*4+2]=tf32f(v.z); dst[j*4+3]=tf32f(v.w);
                }
            }
            __syncthreads();
            float d[4] = {0.f,0.f,0.f,0.f};
            #pragma unroll
            for (int kk=0;kk<8;kk++){
                float4 a = wasv[kk*32 + lane];
                u32 b0 = bits(xs[(kk*8+la)*XS2_S + w*8 + lq]);
                u32 b1 = bits(xs[(kk*8+la+4)*XS2_S + w*8 + lq]);
                mma8(d, bits(a.x),bits(a.y),bits(a.z),bits(a.w), b0,b1);
            }
            int m = r*8 + 2*la;      // warp w = patch w
            *(float2*)&hs[lq*H2_CS     + w*H2_PS + m] = make_float2(tf32f(d[0]), tf32f(d[1]));
            *(float2*)&hs[(lq+8)*H2_CS + w*H2_PS + m] = make_float2(tf32f(d[2]), tf32f(d[3]));
        }
        __syncthreads();

        // ---- Phase 2: u_patch = Gm @ h_patch (warp handles 2 channels) ------
        for (int ci=0; ci<2; ci++){
            int chl = w*2 + ci;
            const float4* ga = &g_ga[((size_t)((ocg*16+chl)*8))*4*32 + lane];
            float d2[4][4];
            #pragma unroll
            for (int mt=0;mt<4;mt++){ d2[mt][0]=d2[mt][1]=d2[mt][2]=d2[mt][3]=0.f; }
            #pragma unroll
            for (int kk=0;kk<8;kk++){
                u32 b0 = bits(hs[chl*H2_CS + lq*H2_PS + kk*8+la]);      // patch=lq
                u32 b1 = bits(hs[chl*H2_CS + lq*H2_PS + kk*8+la+4]);
                #pragma unroll
                for (int mt=0;mt<4;mt++){
                    float4 a = ga[(kk*4+mt)*32];
                    mma8(d2[mt], bits(a.x),bits(a.y),bits(a.z),bits(a.w), b0,b1);
                }
            }
            // D: M=64 (pixel index m), N=8 (patches). lane rows mt*16+lq(,+8),
            // cols (patches) 2la, 2la+1. pixel (n1,n2)=(m>>3,m&7).
            float* uc = ub + (size_t)chl*HW + co;
            #pragma unroll
            for (int mt=0;mt<4;mt++){
                int m0 = mt*16 + lq, m1 = m0 + 8;
                uc[(m0>>3)*WWC + (2*la)*8   + (m0&7)] = d2[mt][0];
                uc[(m0>>3)*WWC + (2*la+1)*8 + (m0&7)] = d2[mt][1];
                uc[(m1>>3)*WWC + (2*la)*8   + (m1&7)] = d2[mt][2];
                uc[(m1>>3)*WWC + (2*la+1)*8 + (m1&7)] = d2[mt][3];
            }
        }
        __syncthreads();
    }
}

// ---------------- K3: depthwise 3x3 (SAME) + exact GELU gate -----------------
__global__ __launch_bounds__(256) void k3_dwgelu(const float* __restrict__ w_dw){
    __shared__ float su[2][18][258];
    int yt = blockIdx.x, i = blockIdx.y, b = blockIdx.z;
    int t = threadIdx.x;
    int y0 = yt*16;
    const float* u1 = g_u + (size_t)(b*C2C + i)*HW;
    const float* u2 = g_u + (size_t)(b*C2C + i + HFC)*HW;
    for (int rr=0; rr<18; rr++){
        int y = y0 + rr - 1;
        bool ok = (y>=0 && y<HH);
        su[0][rr][t+1] = ok ? u1[y*WWC + t] : 0.f;
        su[1][rr][t+1] = ok ? u2[y*WWC + t] : 0.f;
    }
    if (t < 18){ su[0][t][0]=0.f; su[0][t][257]=0.f; su[1][t][0]=0.f; su[1][t][257]=0.f; }
    __syncthreads();
    float wA[9], wB[9];
    #pragma unroll
    for (int k=0;k<9;k++){ wA[k]=w_dw[i*9+k]; wB[k]=w_dw[(i+HFC)*9+k]; }
    float* gb = g_g + (size_t)(b*HFC + i)*HW;
    for (int r=0;r<16;r++){
        float d1=0.f, d2=0.f;
        #pragma unroll
        for (int dy=0;dy<3;dy++){
            #pragma unroll
            for (int dx=0;dx<3;dx++){
                d1 = fmaf(wA[dy*3+dx], su[0][r+dy][t+dx], d1);
                d2 = fmaf(wB[dy*3+dx], su[1][r+dy][t+dx], d2);
            }
        }
        float ge = 0.5f*d1*(1.f + erff(d1*0.70710678118654752f));
        gb[(y0+r)*WWC + t] = ge*d2;
    }
}

// ---------------- K4: out-projection (register-tiled FMA2 GEMM) --------------
__global__ __launch_bounds__(256) void k4_outproj(float* __restrict__ out){
    __shared__ float gs[32*128];         // 16KB
    int b = blockIdx.y; int px0 = blockIdx.x*128;
    int t = threadIdx.x;
    int pxt = t & 31, ocg = t >> 5;
    u64 acc[4][4];
    #pragma unroll
    for (int p=0;p<4;p++)
        #pragma unroll
        for (int j=0;j<4;j++) acc[p][j]=0ULL;

    const float* gb = g_g + (size_t)b*HFC*HW + px0;
    for (int kc=0;kc<4;kc++){
        __syncthreads();
        for (int idx=t; idx<32*128; idx+=256){
            int ii = idx>>7, p = idx&127;
            gs[idx] = gb[(size_t)(kc*32+ii)*HW + p];
        }
        __syncthreads();
        #pragma unroll 4
        for (int ii=0; ii<32; ii++){
            float4 xv = *(const float4*)&gs[ii*128 + pxt*4];
            u64 xp0 = pk(xv.x,xv.x), xp1 = pk(xv.y,xv.y);
            u64 xp2 = pk(xv.z,xv.z), xp3 = pk(xv.w,xv.w);
            const u64* wr = &g_wo[(kc*32+ii)*32 + ocg*4];
            #pragma unroll
            for (int j=0;j<4;j++){
                u64 w = __ldg(&wr[j]);
                fma2(acc[0][j], xp0, w);
                fma2(acc[1][j], xp1, w);
                fma2(acc[2][j], xp2, w);
                fma2(acc[3][j], xp3, w);
            }
        }
    }
    float* ob = out + (size_t)b*DIMC*HW + px0;
    #pragma unroll
    for (int j=0;j<4;j++){
        int jj = ocg*4 + j;
        float2 v0=upk(acc[0][j]), v1=upk(acc[1][j]), v2=upk(acc[2][j]), v3=upk(acc[3][j]);
        *(float4*)&ob[(size_t)(2*jj)*HW   + pxt*4] = make_float4(v0.x, v1.x, v2.x, v3.x);
        *(float4*)&ob[(size_t)(2*jj+1)*HW + pxt*4] = make_float4(v0.y, v1.y, v2.y, v3.y);
    }
}

// -----------------------------------------------------------------------------
extern "C" void kernel_launch(void* const* d_in, const int* in_sizes, int n_in,
                              void* d_out, int out_size){
    const float* x     = (const float*)d_in[0];
    const float* w_in  = (const float*)d_in[1];
    const float* w_dw  = (const float*)d_in[2];
    const float* filt  = (const float*)d_in[3];
    const float* w_out = (const float*)d_in[4];
    float* out = (float*)d_out;

    const int smem12 = (1024 + 64*XS2_S + 16*H2_CS) * 4;   // 59,904 B
    cudaFuncSetAttribute(k12_fused, cudaFuncAttributeMaxDynamicSharedMemorySize, smem12);

    k0_spectral<<<256, 256>>>(filt);
    k0_packw   <<<16, 256>>>(w_in, w_out);
    k12_fused  <<<dim3(16,64,4), 256, smem12>>>(x);
    k3_dwgelu  <<<dim3(16,128,4), 256>>>(w_dw);
    k4_outproj <<<dim3(512,4),    256>>>(out);
}

// round 13
// speedup vs baseline: 2.9010x; 1.2670x over previous
#include <cuda_runtime.h>
#include <math.h>

#define BATCH 4
#define DIMC  64
#define HFC   128
#define C2C   256
#define HH    256
#define WWC   256
#define HW    (HH*WWC)   // 65536

typedef unsigned int u32;
typedef unsigned long long u64;

// K12 smem geometry (floats)
#define XCH  2304           // one chunk buffer: 32ch x 72 stride
#define H2_PS 72            // hs patch stride
#define H2_CS 584           // hs channel stride (8*72+8; %32==8 -> conflict-free)

// ---------------- scratch (device globals: allocation-free rule) -------------
__device__ float  g_u[(size_t)BATCH*C2C*HW];          // spectral output (268 MB)
__device__ float  g_g[(size_t)BATCH*HFC*HW];          // gated output    (134 MB)
__device__ float4 g_ga[(size_t)C2C*8*4*32];           // conv-G A-fragments (4 MB)
__device__ float4 g_wa[16*8*32];                      // w_in A-fragments
__device__ u64    g_wo[128*32];                       // packed w_out

// ---------------- helpers ----------------------------------------------------
__device__ __forceinline__ u32 tf32b(float x){
    u32 r; asm("cvt.rna.tf32.f32 %0, %1;" : "=r"(r) : "f"(x)); return r;
}
__device__ __forceinline__ float tf32f(float x){ return __uint_as_float(tf32b(x)); }
__device__ __forceinline__ u32 bits(float x){ return __float_as_uint(x); }

__device__ __forceinline__ void mma8(float* d, u32 a0,u32 a1,u32 a2,u32 a3, u32 b0,u32 b1){
    asm("mma.sync.aligned.m16n8k8.row.col.f32.tf32.tf32.f32 "
        "{%0,%1,%2,%3},{%4,%5,%6,%7},{%8,%9},{%0,%1,%2,%3};"
        : "+f"(d[0]),"+f"(d[1]),"+f"(d[2]),"+f"(d[3])
        : "r"(a0),"r"(a1),"r"(a2),"r"(a3),"r"(b0),"r"(b1));
}

__device__ __forceinline__ u64 pk(float lo, float hi){
    u64 r; asm("mov.b64 %0, {%1,%2};" : "=l"(r) : "f"(lo), "f"(hi)); return r;
}
__device__ __forceinline__ float2 upk(u64 v){
    float2 r; asm("mov.b64 {%0,%1}, %2;" : "=f"(r.x), "=f"(r.y) : "l"(v)); return r;
}
__device__ __forceinline__ void fma2(u64& d, u64 a, u64 b){
    asm("fma.rn.f32x2 %0, %1, %2, %0;" : "+l"(d) : "l"(a), "l"(b));
}
__device__ __forceinline__ void cp16(u32 smem_dst, const void* gsrc){
    asm volatile("cp.async.cg.shared.global [%0], [%1], 16;"
                 :: "r"(smem_dst), "l"(gsrc) : "memory");
}
__device__ __forceinline__ void cp_commit(){
    asm volatile("cp.async.commit_group;" ::: "memory");
}
__device__ __forceinline__ void cp_wait1(){
    asm volatile("cp.async.wait_group 1;" ::: "memory");
}
__device__ __forceinline__ void cp_wait0(){
    asm volatile("cp.async.wait_group 0;" ::: "memory");
}

// ---------------- K0: spectral filter -> conv-G MMA A-fragments --------------
// g_c[n1,n2] = (1/64) * sum_{k1,k2} G(k1,k2) cos(pi/4*(k1*n1+k2*n2)),
// G = Hermitian extension of F with symmetrization at k2 in {0,4}.
// Conv matrix Gm[n][m] = g[(n1-m1)&7][(n2-m2)&7];  u_patch = Gm @ h_patch.
__global__ void k0_spectral(const float* __restrict__ filt){
    __shared__ float gs[64];
    int c = blockIdx.x, t = threadIdx.x;
    if (t < 64){
        int n1 = t >> 3, n2 = t & 7;
        const float* F = filt + c*40;   // [8][5]
        float s = 0.f;
        for (int k1=0;k1<8;k1++){
            for (int k2=0;k2<8;k2++){
                float Gv;
                if (k2>=1 && k2<=3)      Gv = F[k1*5+k2];
                else if (k2>=5)          Gv = F[((8-k1)&7)*5 + (8-k2)];
                else                     Gv = 0.5f*(F[k1*5+k2] + F[((8-k1)&7)*5 + k2]);
                int m = (k1*n1 + k2*n2) & 7;
                s += Gv * cospif(0.25f * (float)m);
            }
        }
        gs[t] = s * (1.f/64.f);
    }
    __syncthreads();
    for (int i=t; i<8*4*32; i+=256){
        int kk = i>>7, mt = (i>>5)&3, lane = i&31;
        int lq = lane>>2, la = lane&3;
        int n0 = mt*16+lq, n1r = n0+8;
        int m0 = kk*8+la,  m1c = m0+4;
        #define GM(n,m) gs[ ((((n)>>3)-((m)>>3))&7)*8 + ((((n)&7)-((m)&7))&7) ]
        g_ga[((size_t)(c*8+kk)*4 + mt)*32 + lane] =
            make_float4(tf32f(GM(n0,m0)), tf32f(GM(n1r,m0)),
                        tf32f(GM(n0,m1c)), tf32f(GM(n1r,m1c)));
        #undef GM
    }
}

// ---------------- K0b: pack w_in A-fragments + w_out pairs -------------------
__global__ void k0_packw(const float* __restrict__ w_in, const float* __restrict__ w_out){
    int idx = blockIdx.x*256 + threadIdx.x;      // 16*256 = 4096
    {
        int ocg = idx>>8, kk = (idx>>5)&7, lane = idx&31;
        int lq = lane>>2, la = lane&3;
        int o = ocg*16, k = kk*8;
        g_wa[idx] = make_float4(
            tf32f(w_in[(o+lq)*DIMC + k+la]),
            tf32f(w_in[(o+lq+8)*DIMC + k+la]),
            tf32f(w_in[(o+lq)*DIMC + k+la+4]),
            tf32f(w_in[(o+lq+8)*DIMC + k+la+4]));
    }
    if (idx < 128*32){
        int ii = idx >> 5, j = idx & 31;
        g_wo[idx] = pk(w_out[(2*j)*HFC + ii], w_out[(2*j+1)*HFC + ii]);
    }
}

// ---------------- K12: fused in-proj GEMM + spectral conv GEMM (tf32 MMA) ----
// 8-row x 128-col strip per block as two 64-col halves; K split into two
// 32-channel chunks; cp.async 3-stage pipeline; tf32 cvt at read time
// (bit-identical to cvt-at-store). 69KB smem -> 3 CTAs/SM.
__global__ __launch_bounds__(256, 3) void k12_fused(const float* __restrict__ x){
    extern __shared__ float sm[];
    float* was = sm;                    // [8][32] float4 (4KB)
    float* xs  = sm + 1024;             // 3 x XCH (27KB)
    float* hs  = xs + 3*XCH;            // 16ch x 8p x 64m (37.4KB)
    int ocg = blockIdx.x;
    int s   = blockIdx.y;
    int b   = blockIdx.z;
    int t = threadIdx.x, lane = t & 31, w = t >> 5;
    int la = lane & 3, lq = lane >> 2;

    float4* wasv = (float4*)was;
    wasv[t] = g_wa[ocg*256 + t];

    int s8 = (s>>1)*8, cbase = (s&1)*128;
    const float* xb = x + (size_t)b*DIMC*HW + (size_t)s8*WWC + cbase;
    float* ub = g_u + (size_t)(b*C2C + ocg*16)*HW + (size_t)s8*WWC + cbase;

    u32 xs_u = (u32)__cvta_generic_to_shared(xs);
    int ch0 = t>>4, seg = t&15;          // thread copies ch0 and ch0+16, 16B each

    // issue one chunk's cp.asyncs (ic: row=ic>>1, khalf=ic&1)
    #define ISSUE(ic) do{                                                        \
        int row_ = (ic)>>1, kh_ = (ic)&1;                                        \
        int r_ = row_&7, co_ = (row_>>3)*64;                                     \
        const float* s0_ = xb + (size_t)(kh_*32+ch0)*HW + r_*WWC + co_ + seg*4;  \
        u32 d0_ = xs_u + (((ic)%3)*XCH + ch0*72 + seg*4)*4;                      \
        cp16(d0_, s0_);                                                          \
        cp16(d0_ + 16*72*4, s0_ + (size_t)16*HW);                                \
        cp_commit();                                                             \
    }while(0)

    ISSUE(0); ISSUE(1);

    float d[4];
    for (int ic=0; ic<32; ic++){
        int kh = ic&1, r = (ic>>1)&7;
        if (ic<31) cp_wait1(); else cp_wait0();
        __syncthreads();            // chunk ic visible; prior buf reads done
        if (ic+2 < 32) ISSUE(ic+2);
        const float* xc = xs + (ic%3)*XCH;
        if (kh==0){ d[0]=0.f; d[1]=0.f; d[2]=0.f; d[3]=0.f; }
        #pragma unroll
        for (int kkl=0;kkl<4;kkl++){
            int kk = kh*4 + kkl;
            float4 a = wasv[kk*32 + lane];
            u32 b0 = tf32b(xc[(kkl*8+la)*72 + w*8 + lq]);
            u32 b1 = tf32b(xc[(kkl*8+la+4)*72 + w*8 + lq]);
            mma8(d, bits(a.x),bits(a.y),bits(a.z),bits(a.w), b0,b1);
        }
        if (kh==1){
            int m = r*8 + 2*la;     // warp w = patch w
            *(float2*)&hs[lq*H2_CS     + w*H2_PS + m] = make_float2(d[0], d[1]);
            *(float2*)&hs[(lq+8)*H2_CS + w*H2_PS + m] = make_float2(d[2], d[3]);
        }

        if (ic==15 || ic==31){
            int co = (ic>>4)*64;
            __syncthreads();        // all hs stores for this half complete
            for (int ci=0; ci<2; ci++){
                int chl = w*2 + ci;
                const float4* ga = &g_ga[((size_t)((ocg*16+chl)*8))*4*32 + lane];
                float d2[4][4];
                #pragma unroll
                for (int mt=0;mt<4;mt++){ d2[mt][0]=d2[mt][1]=d2[mt][2]=d2[mt][3]=0.f; }
                #pragma unroll
                for (int kk=0;kk<8;kk++){
                    u32 b0 = tf32b(hs[chl*H2_CS + lq*H2_PS + kk*8+la]);   // patch=lq
                    u32 b1 = tf32b(hs[chl*H2_CS + lq*H2_PS + kk*8+la+4]);
                    #pragma unroll
                    for (int mt=0;mt<4;mt++){
                        float4 a = ga[(kk*4+mt)*32];
                        mma8(d2[mt], bits(a.x),bits(a.y),bits(a.z),bits(a.w), b0,b1);
                    }
                }
                float* uc = ub + (size_t)chl*HW + co;
                #pragma unroll
                for (int mt=0;mt<4;mt++){
                    int m0 = mt*16 + lq, m1 = m0 + 8;
                    uc[(m0>>3)*WWC + (2*la)*8   + (m0&7)] = d2[mt][0];
                    uc[(m0>>3)*WWC + (2*la+1)*8 + (m0&7)] = d2[mt][1];
                    uc[(m1>>3)*WWC + (2*la)*8   + (m1&7)] = d2[mt][2];
                    uc[(m1>>3)*WWC + (2*la+1)*8 + (m1&7)] = d2[mt][3];
                }
            }
            if (ic==15) __syncthreads();   // conv reads done before next hs writes
        }
    }
    #undef ISSUE
}

// ---------------- K3: depthwise 3x3 (SAME) + exact GELU gate -----------------
__global__ __launch_bounds__(256) void k3_dwgelu(const float* __restrict__ w_dw){
    __shared__ float su[2][18][258];
    int yt = blockIdx.x, i = blockIdx.y, b = blockIdx.z;
    int t = threadIdx.x;
    int y0 = yt*16;
    const float* u1 = g_u + (size_t)(b*C2C + i)*HW;
    const float* u2 = g_u + (size_t)(b*C2C + i + HFC)*HW;
    for (int rr=0; rr<18; rr++){
        int y = y0 + rr - 1;
        bool ok = (y>=0 && y<HH);
        su[0][rr][t+1] = ok ? u1[y*WWC + t] : 0.f;
        su[1][rr][t+1] = ok ? u2[y*WWC + t] : 0.f;
    }
    if (t < 18){ su[0][t][0]=0.f; su[0][t][257]=0.f; su[1][t][0]=0.f; su[1][t][257]=0.f; }
    __syncthreads();
    float wA[9], wB[9];
    #pragma unroll
    for (int k=0;k<9;k++){ wA[k]=w_dw[i*9+k]; wB[k]=w_dw[(i+HFC)*9+k]; }
    float* gb = g_g + (size_t)(b*HFC + i)*HW;
    for (int r=0;r<16;r++){
        float d1=0.f, d2=0.f;
        #pragma unroll
        for (int dy=0;dy<3;dy++){
            #pragma unroll
            for (int dx=0;dx<3;dx++){
                d1 = fmaf(wA[dy*3+dx], su[0][r+dy][t+dx], d1);
                d2 = fmaf(wB[dy*3+dx], su[1][r+dy][t+dx], d2);
            }
        }
        float ge = 0.5f*d1*(1.f + erff(d1*0.70710678118654752f));
        gb[(y0+r)*WWC + t] = ge*d2;
    }
}

// ---------------- K4: out-projection (register-tiled FMA2 GEMM) --------------
__global__ __launch_bounds__(256) void k4_outproj(float* __restrict__ out){
    __shared__ float gs[32*128];         // 16KB
    int b = blockIdx.y; int px0 = blockIdx.x*128;
    int t = threadIdx.x;
    int pxt = t & 31, ocg = t >> 5;
    u64 acc[4][4];
    #pragma unroll
    for (int p=0;p<4;p++)
        #pragma unroll
        for (int j=0;j<4;j++) acc[p][j]=0ULL;

    const float* gb = g_g + (size_t)b*HFC*HW + px0;
    for (int kc=0;kc<4;kc++){
        __syncthreads();
        for (int idx=t; idx<32*128; idx+=256){
            int ii = idx>>7, p = idx&127;
            gs[idx] = gb[(size_t)(kc*32+ii)*HW + p];
        }
        __syncthreads();
        #pragma unroll 4
        for (int ii=0; ii<32; ii++){
            float4 xv = *(const float4*)&gs[ii*128 + pxt*4];
            u64 xp0 = pk(xv.x,xv.x), xp1 = pk(xv.y,xv.y);
            u64 xp2 = pk(xv.z,xv.z), xp3 = pk(xv.w,xv.w);
            const u64* wr = &g_wo[(kc*32+ii)*32 + ocg*4];
            #pragma unroll
            for (int j=0;j<4;j++){
                u64 w = __ldg(&wr[j]);
                fma2(acc[0][j], xp0, w);
                fma2(acc[1][j], xp1, w);
                fma2(acc[2][j], xp2, w);
                fma2(acc[3][j], xp3, w);
            }
        }
    }
    float* ob = out + (size_t)b*DIMC*HW + px0;
    #pragma unroll
    for (int j=0;j<4;j++){
        int jj = ocg*4 + j;
        float2 v0=upk(acc[0][j]), v1=upk(acc[1][j]), v2=upk(acc[2][j]), v3=upk(acc[3][j]);
        *(float4*)&ob[(size_t)(2*jj)*HW   + pxt*4] = make_float4(v0.x, v1.x, v2.x, v3.x);
        *(float4*)&ob[(size_t)(2*jj+1)*HW + pxt*4] = make_float4(v0.y, v1.y, v2.y, v3.y);
    }
}

// -----------------------------------------------------------------------------
extern "C" void kernel_launch(void* const* d_in, const int* in_sizes, int n_in,
                              void* d_out, int out_size){
    const float* x     = (const float*)d_in[0];
    const float* w_in  = (const float*)d_in[1];
    const float* w_dw  = (const float*)d_in[2];
    const float* filt  = (const float*)d_in[3];
    const float* w_out = (const float*)d_in[4];
    float* out = (float*)d_out;

    const int smem12 = (1024 + 3*XCH + 16*H2_CS) * 4;   // 69,248 B
    cudaFuncSetAttribute(k12_fused, cudaFuncAttributeMaxDynamicSharedMemorySize, smem12);

    k0_spectral<<<256, 256>>>(filt);
    k0_packw   <<<16, 256>>>(w_in, w_out);
    k12_fused  <<<dim3(16,64,4), 256, smem12>>>(x);
    k3_dwgelu  <<<dim3(16,128,4), 256>>>(w_dw);
    k4_outproj <<<dim3(512,4),    256>>>(out);
}

// round 16
// speedup vs baseline: 3.2169x; 1.1089x over previous
#include <cuda_runtime.h>
#include <math.h>

#define BATCH 4
#define DIMC  64
#define HFC   128
#define C2C   256
#define HH    256
#define WWC   256
#define HW    (HH*WWC)   // 65536

typedef unsigned int u32;
typedef unsigned long long u64;

// K12 smem geometry (floats)
#define XCH  2304           // one chunk buffer: 32ch x 72 stride
#define H2_PS 72            // hs patch stride
#define H2_CS 584           // hs channel stride (8*72+8; %32==8 -> conflict-free)

// ---------------- scratch (device globals: allocation-free rule) -------------
__device__ float  g_u[(size_t)BATCH*C2C*HW];          // spectral output (268 MB)
__device__ float  g_g[(size_t)BATCH*HFC*HW];          // gated output    (134 MB)
__device__ float4 g_ga[(size_t)C2C*8*4*32];           // conv-G A-fragments (4 MB)
__device__ float4 g_wa[16*8*32];                      // w_in A-fragments
__device__ float4 g_wh[4*16*32];                      // w_out A-fragments (hi)
__device__ float4 g_wl[4*16*32];                      // w_out A-fragments (lo)

// ---------------- helpers ----------------------------------------------------
__device__ __forceinline__ u32 tf32b(float x){
    u32 r; asm("cvt.rna.tf32.f32 %0, %1;" : "=r"(r) : "f"(x)); return r;
}
__device__ __forceinline__ float tf32f(float x){ return __uint_as_float(tf32b(x)); }
__device__ __forceinline__ u32 bits(float x){ return __float_as_uint(x); }

__device__ __forceinline__ void mma8(float* d, u32 a0,u32 a1,u32 a2,u32 a3, u32 b0,u32 b1){
    asm("mma.sync.aligned.m16n8k8.row.col.f32.tf32.tf32.f32 "
        "{%0,%1,%2,%3},{%4,%5,%6,%7},{%8,%9},{%0,%1,%2,%3};"
        : "+f"(d[0]),"+f"(d[1]),"+f"(d[2]),"+f"(d[3])
        : "r"(a0),"r"(a1),"r"(a2),"r"(a3),"r"(b0),"r"(b1));
}

__device__ __forceinline__ void cp16(u32 smem_dst, const void* gsrc){
    asm volatile("cp.async.cg.shared.global [%0], [%1], 16;"
                 :: "r"(smem_dst), "l"(gsrc) : "memory");
}
__device__ __forceinline__ void cp_commit(){
    asm volatile("cp.async.commit_group;" ::: "memory");
}
__device__ __forceinline__ void cp_wait1(){
    asm volatile("cp.async.wait_group 1;" ::: "memory");
}
__device__ __forceinline__ void cp_wait0(){
    asm volatile("cp.async.wait_group 0;" ::: "memory");
}

// ---------------- K0: spectral filter -> conv-G MMA A-fragments --------------
// g_c[n1,n2] = (1/64) * sum_{k1,k2} G(k1,k2) cos(pi/4*(k1*n1+k2*n2)),
// G = Hermitian extension of F with symmetrization at k2 in {0,4}.
// Conv matrix Gm[n][m] = g[(n1-m1)&7][(n2-m2)&7];  u_patch = Gm @ h_patch.
__global__ void k0_spectral(const float* __restrict__ filt){
    __shared__ float gs[64];
    int c = blockIdx.x, t = threadIdx.x;
    if (t < 64){
        int n1 = t >> 3, n2 = t & 7;
        const float* F = filt + c*40;   // [8][5]
        float s = 0.f;
        for (int k1=0;k1<8;k1++){
            for (int k2=0;k2<8;k2++){
                float Gv;
                if (k2>=1 && k2<=3)      Gv = F[k1*5+k2];
                else if (k2>=5)          Gv = F[((8-k1)&7)*5 + (8-k2)];
                else                     Gv = 0.5f*(F[k1*5+k2] + F[((8-k1)&7)*5 + k2]);
                int m = (k1*n1 + k2*n2) & 7;
                s += Gv * cospif(0.25f * (float)m);
            }
        }
        gs[t] = s * (1.f/64.f);
    }
    __syncthreads();
    for (int i=t; i<8*4*32; i+=256){
        int kk = i>>7, mt = (i>>5)&3, lane = i&31;
        int lq = lane>>2, la = lane&3;
        int n0 = mt*16+lq, n1r = n0+8;
        int m0 = kk*8+la,  m1c = m0+4;
        #define GM(n,m) gs[ ((((n)>>3)-((m)>>3))&7)*8 + ((((n)&7)-((m)&7))&7) ]
        g_ga[((size_t)(c*8+kk)*4 + mt)*32 + lane] =
            make_float4(tf32f(GM(n0,m0)), tf32f(GM(n1r,m0)),
                        tf32f(GM(n0,m1c)), tf32f(GM(n1r,m1c)));
        #undef GM
    }
}

// ---------------- K0b: pack w_in A-fragments + split w_out fragments ---------
__global__ void k0_packw(const float* __restrict__ w_in, const float* __restrict__ w_out){
    int idx = blockIdx.x*256 + threadIdx.x;      // 16*256 = 4096
    {
        int ocg = idx>>8, kk = (idx>>5)&7, lane = idx&31;
        int lq = lane>>2, la = lane&3;
        int o = ocg*16, k = kk*8;
        g_wa[idx] = make_float4(
            tf32f(w_in[(o+lq)*DIMC + k+la]),
            tf32f(w_in[(o+lq+8)*DIMC + k+la]),
            tf32f(w_in[(o+lq)*DIMC + k+la+4]),
            tf32f(w_in[(o+lq+8)*DIMC + k+la+4]));
    }
    if (idx < 4*16*32){
        int mt = idx>>9, kk = (idx>>5)&15, lane = idx&31;
        int lq = lane>>2, la = lane&3;
        int o = mt*16, k = kk*8;
        float v0 = w_out[(o+lq)*HFC   + k+la];
        float v1 = w_out[(o+lq+8)*HFC + k+la];
        float v2 = w_out[(o+lq)*HFC   + k+la+4];
        float v3 = w_out[(o+lq+8)*HFC + k+la+4];
        float h0=tf32f(v0), h1=tf32f(v1), h2=tf32f(v2), h3=tf32f(v3);
        g_wh[idx] = make_float4(h0,h1,h2,h3);
        g_wl[idx] = make_float4(tf32f(v0-h0), tf32f(v1-h1), tf32f(v2-h2), tf32f(v3-h3));
    }
}

// ---------------- K12: fused in-proj GEMM + spectral conv GEMM (tf32 MMA) ----
// 8-row x 128-col strip per block as two 64-col halves; K split into two
// 32-channel chunks; cp.async 3-stage pipeline; tf32 cvt at read time.
__global__ __launch_bounds__(256, 3) void k12_fused(const float* __restrict__ x){
    extern __shared__ float sm[];
    float* was = sm;                    // [8][32] float4 (4KB)
    float* xs  = sm + 1024;             // 3 x XCH (27KB)
    float* hs  = xs + 3*XCH;            // 16ch x 8p x 64m (37.4KB)
    int ocg = blockIdx.x;
    int s   = blockIdx.y;
    int b   = blockIdx.z;
    int t = threadIdx.x, lane = t & 31, w = t >> 5;
    int la = lane & 3, lq = lane >> 2;

    float4* wasv = (float4*)was;
    wasv[t] = g_wa[ocg*256 + t];

    int s8 = (s>>1)*8, cbase = (s&1)*128;
    const float* xb = x + (size_t)b*DIMC*HW + (size_t)s8*WWC + cbase;
    float* ub = g_u + (size_t)(b*C2C + ocg*16)*HW + (size_t)s8*WWC + cbase;

    u32 xs_u = (u32)__cvta_generic_to_shared(xs);
    int ch0 = t>>4, seg = t&15;          // thread copies ch0 and ch0+16, 16B each

    #define ISSUE(ic) do{                                                        \
        int row_ = (ic)>>1, kh_ = (ic)&1;                                        \
        int r_ = row_&7, co_ = (row_>>3)*64;                                     \
        const float* s0_ = xb + (size_t)(kh_*32+ch0)*HW + r_*WWC + co_ + seg*4;  \
        u32 d0_ = xs_u + (((ic)%3)*XCH + ch0*72 + seg*4)*4;                      \
        cp16(d0_, s0_);                                                          \
        cp16(d0_ + 16*72*4, s0_ + (size_t)16*HW);                                \
        cp_commit();                                                             \
    }while(0)

    ISSUE(0); ISSUE(1);

    float d[4];
    for (int ic=0; ic<32; ic++){
        int kh = ic&1, r = (ic>>1)&7;
        if (ic<31) cp_wait1(); else cp_wait0();
        __syncthreads();            // chunk ic visible; prior buf reads done
        if (ic+2 < 32) ISSUE(ic+2);
        const float* xc = xs + (ic%3)*XCH;
        if (kh==0){ d[0]=0.f; d[1]=0.f; d[2]=0.f; d[3]=0.f; }
        #pragma unroll
        for (int kkl=0;kkl<4;kkl++){
            int kk = kh*4 + kkl;
            float4 a = wasv[kk*32 + lane];
            u32 b0 = tf32b(xc[(kkl*8+la)*72 + w*8 + lq]);
            u32 b1 = tf32b(xc[(kkl*8+la+4)*72 + w*8 + lq]);
            mma8(d, bits(a.x),bits(a.y),bits(a.z),bits(a.w), b0,b1);
        }
        if (kh==1){
            int m = r*8 + 2*la;     // warp w = patch w
            *(float2*)&hs[lq*H2_CS     + w*H2_PS + m] = make_float2(d[0], d[1]);
            *(float2*)&hs[(lq+8)*H2_CS + w*H2_PS + m] = make_float2(d[2], d[3]);
        }

        if (ic==15 || ic==31){
            int co = (ic>>4)*64;
            __syncthreads();        // all hs stores for this half complete
            for (int ci=0; ci<2; ci++){
                int chl = w*2 + ci;
                const float4* ga = &g_ga[((size_t)((ocg*16+chl)*8))*4*32 + lane];
                float d2[4][4];
                #pragma unroll
                for (int mt=0;mt<4;mt++){ d2[mt][0]=d2[mt][1]=d2[mt][2]=d2[mt][3]=0.f; }
                #pragma unroll
                for (int kk=0;kk<8;kk++){
                    u32 b0 = tf32b(hs[chl*H2_CS + lq*H2_PS + kk*8+la]);   // patch=lq
                    u32 b1 = tf32b(hs[chl*H2_CS + lq*H2_PS + kk*8+la+4]);
                    #pragma unroll
                    for (int mt=0;mt<4;mt++){
                        float4 a = ga[(kk*4+mt)*32];
                        mma8(d2[mt], bits(a.x),bits(a.y),bits(a.z),bits(a.w), b0,b1);
                    }
                }
                float* uc = ub + (size_t)chl*HW + co;
                #pragma unroll
                for (int mt=0;mt<4;mt++){
                    int m0 = mt*16 + lq, m1 = m0 + 8;
                    uc[(m0>>3)*WWC + (2*la)*8   + (m0&7)] = d2[mt][0];
                    uc[(m0>>3)*WWC + (2*la+1)*8 + (m0&7)] = d2[mt][1];
                    uc[(m1>>3)*WWC + (2*la)*8   + (m1&7)] = d2[mt][2];
                    uc[(m1>>3)*WWC + (2*la+1)*8 + (m1&7)] = d2[mt][3];
                }
            }
            if (ic==15) __syncthreads();   // conv reads done before next hs writes
        }
    }
    #undef ISSUE
}

// ---------------- K3: depthwise 3x3 (SAME) + exact GELU gate -----------------
__global__ __launch_bounds__(256) void k3_dwgelu(const float* __restrict__ w_dw){
    __shared__ float su[2][18][258];
    int yt = blockIdx.x, i = blockIdx.y, b = blockIdx.z;
    int t = threadIdx.x;
    int y0 = yt*16;
    const float* u1 = g_u + (size_t)(b*C2C + i)*HW;
    const float* u2 = g_u + (size_t)(b*C2C + i + HFC)*HW;
    for (int rr=0; rr<18; rr++){
        int y = y0 + rr - 1;
        bool ok = (y>=0 && y<HH);
        su[0][rr][t+1] = ok ? u1[y*WWC + t] : 0.f;
        su[1][rr][t+1] = ok ? u2[y*WWC + t] : 0.f;
    }
    if (t < 18){ su[0][t][0]=0.f; su[0][t][257]=0.f; su[1][t][0]=0.f; su[1][t][257]=0.f; }
    __syncthreads();
    float wA[9], wB[9];
    #pragma unroll
    for (int k=0;k<9;k++){ wA[k]=w_dw[i*9+k]; wB[k]=w_dw[(i+HFC)*9+k]; }
    float* gb = g_g + (size_t)(b*HFC + i)*HW;
    for (int r=0;r<16;r++){
        float d1=0.f, d2=0.f;
        #pragma unroll
        for (int dy=0;dy<3;dy++){
            #pragma unroll
            for (int dx=0;dx<3;dx++){
                d1 = fmaf(wA[dy*3+dx], su[0][r+dy][t+dx], d1);
                d2 = fmaf(wB[dy*3+dx], su[1][r+dy][t+dx], d2);
            }
        }
        float ge = 0.5f*d1*(1.f + erff(d1*0.70710678118654752f));
        gb[(y0+r)*WWC + t] = ge*d2;
    }
}

// ---------------- K4: out-projection (tf32 MMA, Dekker-split 3-pass) ---------
// Block: 128 px x 64 oc, K=128 in 4 chunks of 32. Warp = (m-tile, n-half).
// Split A=w_out and B=g into tf32 hi+lo; hi*hi + hi*lo + lo*hi => ~fp32 exact.
__global__ __launch_bounds__(256) void k4_outproj(float* __restrict__ out){
    __shared__ float gh[32*136], gl[32*136];     // 34.8KB
    int b = blockIdx.y; int px0 = blockIdx.x*128;
    int t = threadIdx.x, lane = t & 31, w = t >> 5;
    int la = lane & 3, lq = lane >> 2;
    int mt = w & 3, nh = w >> 2;

    float d[8][4];
    #pragma unroll
    for (int nt=0;nt<8;nt++){ d[nt][0]=d[nt][1]=d[nt][2]=d[nt][3]=0.f; }

    const float* gb = g_g + (size_t)b*HFC*HW + px0;
    for (int kc=0;kc<4;kc++){
        __syncthreads();
        for (int idx=t; idx<32*128; idx+=256){
            int k = idx>>7, p = idx&127;
            float v = gb[(size_t)(kc*32+k)*HW + p];
            float h = tf32f(v);
            gh[k*136+p] = h;
            gl[k*136+p] = tf32f(v - h);
        }
        __syncthreads();
        #pragma unroll
        for (int kkl=0;kkl<4;kkl++){
            float4 ah = g_wh[(mt*16 + kc*4 + kkl)*32 + lane];
            float4 al = g_wl[(mt*16 + kc*4 + kkl)*32 + lane];
            #pragma unroll
            for (int nt=0;nt<8;nt++){
                int px = nh*64 + nt*8 + lq;
                u32 bh0 = bits(gh[(kkl*8+la)*136 + px]);
                u32 bh1 = bits(gh[(kkl*8+la+4)*136 + px]);
                u32 bl0 = bits(gl[(kkl*8+la)*136 + px]);
                u32 bl1 = bits(gl[(kkl*8+la+4)*136 + px]);
                mma8(d[nt], bits(ah.x),bits(ah.y),bits(ah.z),bits(ah.w), bh0,bh1);
                mma8(d[nt], bits(ah.x),bits(ah.y),bits(ah.z),bits(ah.w), bl0,bl1);
                mma8(d[nt], bits(al.x),bits(al.y),bits(al.z),bits(al.w), bh0,bh1);
            }
        }
    }
    float* ob = out + (size_t)b*DIMC*HW + px0;
    int oc0 = mt*16 + lq;
    #pragma unroll
    for (int nt=0;nt<8;nt++){
        int px = nh*64 + nt*8 + 2*la;
        *(float2*)&ob[(size_t)oc0*HW     + px] = make_float2(d[nt][0], d[nt][1]);
        *(float2*)&ob[(size_t)(oc0+8)*HW + px] = make_float2(d[nt][2], d[nt][3]);
    }
}

// -----------------------------------------------------------------------------
extern "C" void kernel_launch(void* const* d_in, const int* in_sizes, int n_in,
                              void* d_out, int out_size){
    const float* x     = (const float*)d_in[0];
    const float* w_in  = (const float*)d_in[1];
    const float* w_dw  = (const float*)d_in[2];
    const float* filt  = (const float*)d_in[3];
    const float* w_out = (const float*)d_in[4];
    float* out = (float*)d_out;

    const int smem12 = (1024 + 3*XCH + 16*H2_CS) * 4;   // 69,248 B
    cudaFuncSetAttribute(k12_fused, cudaFuncAttributeMaxDynamicSharedMemorySize, smem12);

    k0_spectral<<<256, 256>>>(filt);
    k0_packw   <<<16, 256>>>(w_in, w_out);
    k12_fused  <<<dim3(16,64,4), 256, smem12>>>(x);
    k3_dwgelu  <<<dim3(16,128,4), 256>>>(w_dw);
    k4_outproj <<<dim3(512,4),    256>>>(out);
}